// round 4
// baseline (speedup 1.0000x reference)
#include <cuda_runtime.h>

#define N_NODES 100000
#define NFEAT   64
#define NHID    64
#define NCLASS  16
#define N_EDGES 1600000

// Scratch: aggregation buffer (25.6 MB) as device global (no allocation allowed)
__device__ __align__(16) float g_agg[N_NODES * NFEAT];

// ---------------------------------------------------------------------------
// Kernel 1: agg = (1 + eps) * x        (vectorized float4 stream)
// ---------------------------------------------------------------------------
__global__ void gin_init_kernel(const float4* __restrict__ x4,
                                const float* __restrict__ eps) {
    int i = blockIdx.x * blockDim.x + threadIdx.x;
    if (i < N_NODES * NFEAT / 4) {
        float s = 1.0f + __ldg(eps);
        float4 v = x4[i];
        v.x *= s; v.y *= s; v.z *= s; v.w *= s;
        reinterpret_cast<float4*>(g_agg)[i] = v;
    }
}

// ---------------------------------------------------------------------------
// Kernel 2: agg[dst] += x[src]  over all edges.
// edge_index arrives as int32 (harness downcasts int64): src = ei[0..E),
// dst = ei[E..2E). 16 threads per edge, one float4 vector-RED per 16 bytes.
// ---------------------------------------------------------------------------
__global__ void gin_scatter_kernel(const float4* __restrict__ x4,
                                   const int* __restrict__ ei) {
    long long tid = (long long)blockIdx.x * blockDim.x + threadIdx.x;
    if (tid >= (long long)N_EDGES * 16) return;
    int e = (int)(tid >> 4);
    int q = (int)(tid & 15);
    int s = __ldg(ei + e);            // src node
    int d = __ldg(ei + N_EDGES + e);  // dst node
    if ((unsigned)s >= N_NODES || (unsigned)d >= N_NODES) return;  // safety
    float4 v = x4[s * 16 + q];
    float4* p = reinterpret_cast<float4*>(g_agg + (size_t)d * 64 + (size_t)q * 4);
    atomicAdd(p, v);
}

// ---------------------------------------------------------------------------
// Kernel 3: out = relu(agg @ W1 + b1) @ W2 + b2   (fully fused per node)
// 128 threads/block, one node per thread. Weights + node tile staged in smem.
// Node tile pitch 65 floats -> conflict-free (t + k) % 32 bank pattern.
// Dynamic smem: 4096 + 1024 + 64 + 16 + 128*65 floats = 54,080 bytes.
// ---------------------------------------------------------------------------
extern __shared__ float smem[];

__global__ void gin_mlp_kernel(const float* __restrict__ W1,
                               const float* __restrict__ b1,
                               const float* __restrict__ W2,
                               const float* __restrict__ b2,
                               float* __restrict__ out) {
    float* sW1 = smem;            // [64][64] k-major (matches input layout)
    float* sW2 = smem + 4096;     // [64][16]
    float* sb1 = smem + 5120;     // [64]
    float* sb2 = smem + 5184;     // [16]
    float* sh  = smem + 5200;     // [128][65] node tile, padded pitch

    int t = threadIdx.x;

    for (int i = t; i < 4096; i += 128) sW1[i] = W1[i];
    for (int i = t; i < 1024; i += 128) sW2[i] = W2[i];
    if (t < 64) sb1[t] = b1[t];
    if (t < 16) sb2[t] = b2[t];

    int node0 = blockIdx.x * 128;
    int nrows = N_NODES - node0; if (nrows > 128) nrows = 128;

    // Coalesced tile load: consecutive threads -> consecutive gmem floats
    for (int i = t; i < nrows * 64; i += 128) {
        sh[(i >> 6) * 65 + (i & 63)] = g_agg[(size_t)node0 * 64 + i];
    }
    __syncthreads();

    int node = node0 + t;
    if (node >= N_NODES) return;

    const float* h = sh + t * 65;

    float o[16];
    #pragma unroll
    for (int c = 0; c < 16; c++) o[c] = sb2[c];

    // Hidden units in 4 chunks of 16 to bound register pressure.
    for (int jc = 0; jc < 4; jc++) {
        float acc[16];
        #pragma unroll
        for (int u = 0; u < 16; u++) acc[u] = sb1[jc * 16 + u];

        #pragma unroll 8
        for (int k = 0; k < 64; k++) {
            float hk = h[k];  // conflict-free: bank (t + k) % 32
            const float4* wr = reinterpret_cast<const float4*>(sW1 + k * 64 + jc * 16);
            float4 w0 = wr[0], w1 = wr[1], w2 = wr[2], w3 = wr[3]; // broadcast LDS.128
            acc[ 0] += hk * w0.x; acc[ 1] += hk * w0.y; acc[ 2] += hk * w0.z; acc[ 3] += hk * w0.w;
            acc[ 4] += hk * w1.x; acc[ 5] += hk * w1.y; acc[ 6] += hk * w1.z; acc[ 7] += hk * w1.w;
            acc[ 8] += hk * w2.x; acc[ 9] += hk * w2.y; acc[10] += hk * w2.z; acc[11] += hk * w2.w;
            acc[12] += hk * w3.x; acc[13] += hk * w3.y; acc[14] += hk * w3.z; acc[15] += hk * w3.w;
        }

        #pragma unroll
        for (int u = 0; u < 16; u++) {
            float hr = fmaxf(acc[u], 0.0f);
            const float4* w2r = reinterpret_cast<const float4*>(sW2 + (jc * 16 + u) * 16);
            float4 a = w2r[0], b = w2r[1], c = w2r[2], d = w2r[3];
            o[ 0] += hr * a.x; o[ 1] += hr * a.y; o[ 2] += hr * a.z; o[ 3] += hr * a.w;
            o[ 4] += hr * b.x; o[ 5] += hr * b.y; o[ 6] += hr * b.z; o[ 7] += hr * b.w;
            o[ 8] += hr * c.x; o[ 9] += hr * c.y; o[10] += hr * c.z; o[11] += hr * c.w;
            o[12] += hr * d.x; o[13] += hr * d.y; o[14] += hr * d.z; o[15] += hr * d.w;
        }
    }

    float4* op = reinterpret_cast<float4*>(out + (size_t)node * 16);
    op[0] = make_float4(o[ 0], o[ 1], o[ 2], o[ 3]);
    op[1] = make_float4(o[ 4], o[ 5], o[ 6], o[ 7]);
    op[2] = make_float4(o[ 8], o[ 9], o[10], o[11]);
    op[3] = make_float4(o[12], o[13], o[14], o[15]);
}

// ---------------------------------------------------------------------------
extern "C" void kernel_launch(void* const* d_in, const int* in_sizes, int n_in,
                              void* d_out, int out_size) {
    const float* x   = (const float*)d_in[0];
    const int*   ei  = (const int*)d_in[1];   // int64 downcast to int32 by harness
    const float* eps = (const float*)d_in[2];
    const float* W1  = (const float*)d_in[3];
    const float* b1  = (const float*)d_in[4];
    const float* W2  = (const float*)d_in[5];
    const float* b2  = (const float*)d_in[6];
    float*       out = (float*)d_out;

    // Kernel 1: init agg = (1+eps)*x
    {
        int n = N_NODES * NFEAT / 4;
        gin_init_kernel<<<(n + 255) / 256, 256>>>((const float4*)x, eps);
    }

    // Kernel 2: scatter-add
    {
        long long total = (long long)N_EDGES * 16;
        int blocks = (int)((total + 255) / 256);
        gin_scatter_kernel<<<blocks, 256>>>((const float4*)x, ei);
    }

    // Kernel 3: fused MLP
    {
        size_t shbytes = (size_t)(4096 + 1024 + 64 + 16 + 128 * 65) * sizeof(float);
        cudaFuncSetAttribute(gin_mlp_kernel,
                             cudaFuncAttributeMaxDynamicSharedMemorySize,
                             (int)shbytes);
        int blocks = (N_NODES + 127) / 128;
        gin_mlp_kernel<<<blocks, 128, shbytes>>>(W1, b1, W2, b2, out);
    }
}

// round 5
// speedup vs baseline: 1.1000x; 1.1000x over previous
#include <cuda_runtime.h>

#define N_NODES 100000
#define NFEAT   64
#define N_EDGES 1600000

#define SCAN_BLK 1024
#define N_SCAN_BLOCKS ((N_NODES + SCAN_BLK - 1) / SCAN_BLK)   // 98

// Device-global scratch (no allocation allowed)
__device__ __align__(16) float g_agg[N_NODES * NFEAT];
__device__ int g_count[N_NODES];
__device__ int g_off[N_NODES + 1];
__device__ int g_cursor[N_NODES];
__device__ int g_perm[N_EDGES];
__device__ int g_bsum[N_SCAN_BLOCKS];
__device__ int g_bsumx[N_SCAN_BLOCKS];

// ---------------------------------------------------------------------------
// Pass 1: zero counts
// ---------------------------------------------------------------------------
__global__ void k_zero_counts() {
    int i = blockIdx.x * blockDim.x + threadIdx.x;
    if (i < N_NODES) g_count[i] = 0;
}

// ---------------------------------------------------------------------------
// Pass 2: histogram of dst
// ---------------------------------------------------------------------------
__global__ void k_count(const int* __restrict__ ei) {
    int e = blockIdx.x * blockDim.x + threadIdx.x;
    if (e >= N_EDGES) return;
    int d = __ldg(ei + N_EDGES + e);
    if ((unsigned)d < N_NODES) atomicAdd(&g_count[d], 1);
}

// ---------------------------------------------------------------------------
// Pass 3a: per-block exclusive scan of counts (block = 1024)
// ---------------------------------------------------------------------------
__global__ void k_scan1() {
    __shared__ int sdata[SCAN_BLK];
    int tid = threadIdx.x;
    int i = blockIdx.x * SCAN_BLK + tid;
    int v = (i < N_NODES) ? g_count[i] : 0;
    sdata[tid] = v;
    __syncthreads();
    #pragma unroll
    for (int d = 1; d < SCAN_BLK; d <<= 1) {
        int t = (tid >= d) ? sdata[tid - d] : 0;
        __syncthreads();
        sdata[tid] += t;
        __syncthreads();
    }
    if (i < N_NODES) g_off[i] = sdata[tid] - v;          // exclusive
    if (tid == SCAN_BLK - 1) g_bsum[blockIdx.x] = sdata[tid];
}

// ---------------------------------------------------------------------------
// Pass 3b: serial exclusive scan of the 98 block sums
// ---------------------------------------------------------------------------
__global__ void k_scan2() {
    if (threadIdx.x == 0) {
        int run = 0;
        for (int b = 0; b < N_SCAN_BLOCKS; b++) {
            g_bsumx[b] = run;
            run += g_bsum[b];
        }
    }
}

// ---------------------------------------------------------------------------
// Pass 3c: add block offsets; init cursor; seal g_off[N]
// ---------------------------------------------------------------------------
__global__ void k_scan3() {
    int i = blockIdx.x * blockDim.x + threadIdx.x;
    if (i < N_NODES) {
        int off = g_off[i] + g_bsumx[i >> 10];
        g_off[i] = off;
        g_cursor[i] = off;
    }
    if (i == 0) g_off[N_NODES] = N_EDGES;
}

// ---------------------------------------------------------------------------
// Pass 4: fill permutation: perm[pos] = src, grouped by dst
// ---------------------------------------------------------------------------
__global__ void k_fill(const int* __restrict__ ei) {
    int e = blockIdx.x * blockDim.x + threadIdx.x;
    if (e >= N_EDGES) return;
    int s = __ldg(ei + e);
    int d = __ldg(ei + N_EDGES + e);
    if ((unsigned)d >= N_NODES || (unsigned)s >= N_NODES) return;
    int pos = atomicAdd(&g_cursor[d], 1);
    g_perm[pos] = s;
}

// ---------------------------------------------------------------------------
// Pass 5: segment gather-sum + (1+eps)*x fold-in. 16 threads per node,
// thread q owns float4 chunk q of the 64-float row. Pure loads + one store.
// ---------------------------------------------------------------------------
__global__ void k_gather(const float4* __restrict__ x4,
                         const float* __restrict__ eps) {
    int tid = blockIdx.x * blockDim.x + threadIdx.x;
    int node = tid >> 4;
    int q = tid & 15;
    if (node >= N_NODES) return;

    float s = 1.0f + __ldg(eps);
    float4 a = __ldg(x4 + (size_t)node * 16 + q);
    float4 acc = make_float4(a.x * s, a.y * s, a.z * s, a.w * s);

    int j = g_off[node];
    int end = g_off[node + 1];
    for (; j < end; j++) {
        int src = __ldg(&g_perm[j]);
        float4 v = __ldg(x4 + (size_t)src * 16 + q);
        acc.x += v.x; acc.y += v.y; acc.z += v.z; acc.w += v.w;
    }
    reinterpret_cast<float4*>(g_agg)[(size_t)node * 16 + q] = acc;
}

// ---------------------------------------------------------------------------
// Pass 6: out = relu(agg @ W1 + b1) @ W2 + b2   (fully fused per node)
// ---------------------------------------------------------------------------
extern __shared__ float smem[];

__global__ void gin_mlp_kernel(const float* __restrict__ W1,
                               const float* __restrict__ b1,
                               const float* __restrict__ W2,
                               const float* __restrict__ b2,
                               float* __restrict__ out) {
    float* sW1 = smem;            // [64][64]
    float* sW2 = smem + 4096;     // [64][16]
    float* sb1 = smem + 5120;     // [64]
    float* sb2 = smem + 5184;     // [16]
    float* sh  = smem + 5200;     // [128][65]

    int t = threadIdx.x;

    for (int i = t; i < 4096; i += 128) sW1[i] = W1[i];
    for (int i = t; i < 1024; i += 128) sW2[i] = W2[i];
    if (t < 64) sb1[t] = b1[t];
    if (t < 16) sb2[t] = b2[t];

    int node0 = blockIdx.x * 128;
    int nrows = N_NODES - node0; if (nrows > 128) nrows = 128;

    for (int i = t; i < nrows * 64; i += 128) {
        sh[(i >> 6) * 65 + (i & 63)] = g_agg[(size_t)node0 * 64 + i];
    }
    __syncthreads();

    int node = node0 + t;
    if (node >= N_NODES) return;

    const float* h = sh + t * 65;

    float o[16];
    #pragma unroll
    for (int c = 0; c < 16; c++) o[c] = sb2[c];

    for (int jc = 0; jc < 4; jc++) {
        float acc[16];
        #pragma unroll
        for (int u = 0; u < 16; u++) acc[u] = sb1[jc * 16 + u];

        #pragma unroll 8
        for (int k = 0; k < 64; k++) {
            float hk = h[k];
            const float4* wr = reinterpret_cast<const float4*>(sW1 + k * 64 + jc * 16);
            float4 w0 = wr[0], w1 = wr[1], w2 = wr[2], w3 = wr[3];
            acc[ 0] += hk * w0.x; acc[ 1] += hk * w0.y; acc[ 2] += hk * w0.z; acc[ 3] += hk * w0.w;
            acc[ 4] += hk * w1.x; acc[ 5] += hk * w1.y; acc[ 6] += hk * w1.z; acc[ 7] += hk * w1.w;
            acc[ 8] += hk * w2.x; acc[ 9] += hk * w2.y; acc[10] += hk * w2.z; acc[11] += hk * w2.w;
            acc[12] += hk * w3.x; acc[13] += hk * w3.y; acc[14] += hk * w3.z; acc[15] += hk * w3.w;
        }

        #pragma unroll
        for (int u = 0; u < 16; u++) {
            float hr = fmaxf(acc[u], 0.0f);
            const float4* w2r = reinterpret_cast<const float4*>(sW2 + (jc * 16 + u) * 16);
            float4 a = w2r[0], b = w2r[1], c = w2r[2], d = w2r[3];
            o[ 0] += hr * a.x; o[ 1] += hr * a.y; o[ 2] += hr * a.z; o[ 3] += hr * a.w;
            o[ 4] += hr * b.x; o[ 5] += hr * b.y; o[ 6] += hr * b.z; o[ 7] += hr * b.w;
            o[ 8] += hr * c.x; o[ 9] += hr * c.y; o[10] += hr * c.z; o[11] += hr * c.w;
            o[12] += hr * d.x; o[13] += hr * d.y; o[14] += hr * d.z; o[15] += hr * d.w;
        }
    }

    float4* op = reinterpret_cast<float4*>(out + (size_t)node * 16);
    op[0] = make_float4(o[ 0], o[ 1], o[ 2], o[ 3]);
    op[1] = make_float4(o[ 4], o[ 5], o[ 6], o[ 7]);
    op[2] = make_float4(o[ 8], o[ 9], o[10], o[11]);
    op[3] = make_float4(o[12], o[13], o[14], o[15]);
}

// ---------------------------------------------------------------------------
extern "C" void kernel_launch(void* const* d_in, const int* in_sizes, int n_in,
                              void* d_out, int out_size) {
    const float* x   = (const float*)d_in[0];
    const int*   ei  = (const int*)d_in[1];   // int64 downcast to int32 by harness
    const float* eps = (const float*)d_in[2];
    const float* W1  = (const float*)d_in[3];
    const float* b1  = (const float*)d_in[4];
    const float* W2  = (const float*)d_in[5];
    const float* b2  = (const float*)d_in[6];
    float*       out = (float*)d_out;

    const int EB = (N_EDGES + 255) / 256;          // 6250 blocks over edges
    const int NB = (N_NODES + 255) / 256;          // 391 blocks over nodes

    k_zero_counts<<<NB, 256>>>();
    k_count<<<EB, 256>>>(ei);
    k_scan1<<<N_SCAN_BLOCKS, SCAN_BLK>>>();
    k_scan2<<<1, 32>>>();
    k_scan3<<<NB, 256>>>();
    k_fill<<<EB, 256>>>(ei);

    {
        long long total = (long long)N_NODES * 16;
        int blocks = (int)((total + 255) / 256);
        k_gather<<<blocks, 256>>>((const float4*)x, eps);
    }

    {
        size_t shbytes = (size_t)(4096 + 1024 + 64 + 16 + 128 * 65) * sizeof(float);
        cudaFuncSetAttribute(gin_mlp_kernel,
                             cudaFuncAttributeMaxDynamicSharedMemorySize,
                             (int)shbytes);
        int blocks = (N_NODES + 127) / 128;
        gin_mlp_kernel<<<blocks, 128, shbytes>>>(W1, b1, W2, b2, out);
    }
}